// round 15
// baseline (speedup 1.0000x reference)
#include <cuda_runtime.h>
#include <cuda_fp16.h>
#include <cstdint>

#define HW 16384
#define NTH 512       // 16 warps per CTA; 2 CTAs/SM
#define PTILE 64      // pixels per CTA
#define BPITCH 72     // B smem pitch (halfs): 36 words = 4 mod 32 -> conflict-free ldsm
#define YPITCH 68     // Y smem pitch (floats)
#define NCHUNK 8      // 8 chunks of k=64: W1[0..3] then W2[4..7]

// ---- smem layout (bytes), per CTA ----
#define SM_BH   0                 // Bh fp16 256x72 = 36864; Ys fp32 256x68 = 69632 aliases [0,69632)
#define SM_MSK  69632             // 64
#define SM_POS  69760             // 64 x int16
#define SM_FLG  70016             // ints
#define SM_TOTAL 70080            // x2 CTAs = 140160

// Weights pre-packed in mma A-fragment order:
// g_Wf[(chunk*16 + wd)*4*32 + ks*32 + lane] = uint4{a0,a1,a2,a3} for that lane.
__device__ __align__(16) uint4 g_Wf[NCHUNK * 16 * 4 * 32];

__device__ __host__ __forceinline__ uint32_t hpack2(__half a, __half b) {
    __half2 t = __halves2half2(a, b);
    return *reinterpret_cast<uint32_t*>(&t);
}

// ---------------- weight prep: transpose + fp16 + fragment-order packing ----------------
extern "C" __global__ void prep_weights_kernel(const float* __restrict__ W1,
                                               const float* __restrict__ W2)
{
    int e = blockIdx.x * 256 + threadIdx.x;   // 0..16383
    int lane = e & 31;
    int ks   = (e >> 5) & 3;
    int wd   = (e >> 7) & 15;
    int ch   = e >> 11;                        // 0..7
    const float* W = (ch < 4) ? W1 : W2;       // A[m][k] = W[k*256 + m]
    int kb = (ch & 3) * 64 + ks * 16 + (lane & 3) * 2;
    int m0 = wd * 16 + (lane >> 2);

    uint4 v;
    v.x = hpack2(__float2half_rn(W[kb * 256 + m0]),
                 __float2half_rn(W[(kb + 1) * 256 + m0]));
    v.y = hpack2(__float2half_rn(W[kb * 256 + m0 + 8]),
                 __float2half_rn(W[(kb + 1) * 256 + m0 + 8]));
    v.z = hpack2(__float2half_rn(W[(kb + 8) * 256 + m0]),
                 __float2half_rn(W[(kb + 9) * 256 + m0]));
    v.w = hpack2(__float2half_rn(W[(kb + 8) * 256 + m0 + 8]),
                 __float2half_rn(W[(kb + 9) * 256 + m0 + 8]));
    g_Wf[e] = v;
}

// ---------------- helpers ----------------
__device__ __forceinline__ void ldsm_x4_t(uint32_t* r, uint32_t addr) {
    asm volatile("ldmatrix.sync.aligned.m8n8.x4.trans.shared.b16 {%0,%1,%2,%3}, [%4];"
                 : "=r"(r[0]), "=r"(r[1]), "=r"(r[2]), "=r"(r[3]) : "r"(addr));
}
__device__ __forceinline__ void mma_f16(float* d, uint32_t a0, uint32_t a1,
                                        uint32_t a2, uint32_t a3, const uint32_t* b) {
    asm volatile("mma.sync.aligned.m16n8k16.row.col.f32.f16.f16.f32 "
                 "{%0,%1,%2,%3}, {%4,%5,%6,%7}, {%8,%9}, {%0,%1,%2,%3};"
                 : "+f"(d[0]), "+f"(d[1]), "+f"(d[2]), "+f"(d[3])
                 : "r"(a0), "r"(a1), "r"(a2), "r"(a3), "r"(b[0]), "r"(b[1]));
}

// ---------------- main fused masked-MLP kernel ----------------
extern "C" __global__ void __launch_bounds__(NTH, 2)
mlp_mma_kernel(const float* __restrict__ x,
               const void* __restrict__ mask,
               const float* __restrict__ b1g,
               const float* __restrict__ b2g,
               float* __restrict__ out)
{
    extern __shared__ char smc[];
    const uint32_t sb = (uint32_t)__cvta_generic_to_shared(smc);
    int* flg = (int*)(smc + SM_FLG);
    short* pos = (short*)(smc + SM_POS);

    const int tid = threadIdx.x, lane = tid & 31, wid = tid >> 5;   // wid = wd 0..15
    const int g = lane >> 2, tc = lane & 3;
    const int l15 = lane & 15, l16 = (lane >> 4) * 8;
    const int b = blockIdx.x >> 8, p0 = (blockIdx.x & 255) * PTILE;
    const float* xb = x + (size_t)b * 256 * HW + p0;
    const int gi0 = b * HW + p0;

    // ---- per-CTA mask dtype detection (16 words cover 64 px in all encodings) ----
    if (tid < 16) {
        unsigned w = ((const unsigned*)mask)[gi0 / 4 + tid];
        bool fl = (w == 0x3F800000u);
        bool by = (w > 1u) && !fl;
        unsigned bb = __ballot_sync(0xFFFFu, by);
        if (tid == 0) flg[0] = bb ? 1 : 0;
    }
    __syncthreads();

    if (tid < PTILE) {
        int mv;
        if (flg[0]) mv = (((const unsigned char*)mask)[gi0 + tid] != 0);
        else        mv = (((const int*)mask)[gi0 + tid] != 0);
        smc[SM_MSK + tid] = (char)mv;
    }
    __syncthreads();

    // ---- warp 0: prefix scan over 64 px -> per-pixel pos[] / nc ----
    if (wid == 0) {
        int base = lane * 2;
        int m0 = smc[SM_MSK + base], m1 = smc[SM_MSK + base + 1];
        int c = m0 + m1;
        int sc = c;
        #pragma unroll
        for (int o = 1; o < 32; o <<= 1) {
            int t = __shfl_up_sync(0xFFFFFFFFu, sc, o);
            if (lane >= o) sc += t;
        }
        int run = sc - c;
        pos[base]     = (short)run; run += m0;
        pos[base + 1] = (short)run; run += m1;
        if (lane == 31) flg[1] = run;
    }
    __syncthreads();
    const int nc = flg[1];
    const int ntiles = (nc + 15) >> 4;   // 0..4

    // ---- X load + fp16 convert + compacted store ----
    __half* Bh = (__half*)(smc + SM_BH);
    #pragma unroll 4
    for (int it = 0; it < 8; it++) {
        int e = tid + it * NTH;          // 0..4095 float4s
        int c = e >> 4;                  // 16 float4 per 64-px row
        int q = (e & 15) * 4;
        float4 v = *(const float4*)(xb + (size_t)c * HW + q);
        float vv[4] = {v.x, v.y, v.z, v.w};
        #pragma unroll
        for (int i = 0; i < 4; i++) {
            if (smc[SM_MSK + q + i])
                Bh[c * BPITCH + pos[q + i]] = __float2half_rn(vv[i]);
        }
    }
    __syncthreads();   // X tile visible to all warps before B-ldsm

    float acc[4][2][4];
    #pragma unroll
    for (int s = 0; s < 4; s++)
        #pragma unroll
        for (int jl = 0; jl < 2; jl++)
            #pragma unroll
            for (int r = 0; r < 4; r++) acc[s][jl][r] = 0.f;

    // warp-constant bases
    const uint4* __restrict__ wfb = g_Wf + (wid << 7) + lane;   // +ks*32; +kc*2048
    const uint32_t b_base = sb + SM_BH + (uint32_t)(l15 * BPITCH + l16) * 2;

    // ---- 8-chunk K loop (k=64 each): chunks 0-3 = GEMM1, 4-7 = GEMM2 (barrier-free) ----
    #pragma unroll 1
    for (int kc = 0; kc < NCHUNK; kc++) {
        if (kc == 4) {
            __syncthreads();   // all warps done reading X from Bh
            // ---- H epilogue: bias + relu -> fp16 into Bh ----
            int r0 = wid * 16 + g;
            float bv0 = b1g[r0], bv1 = b1g[r0 + 8];
            #pragma unroll
            for (int s = 0; s < 4; s++) {
                if (s >= ntiles) break;
                #pragma unroll
                for (int jl = 0; jl < 2; jl++) {
                    int px = s * 16 + jl * 8 + tc * 2;
                    float h00 = fmaxf(acc[s][jl][0] + bv0, 0.f);
                    float h01 = fmaxf(acc[s][jl][1] + bv0, 0.f);
                    float h10 = fmaxf(acc[s][jl][2] + bv1, 0.f);
                    float h11 = fmaxf(acc[s][jl][3] + bv1, 0.f);
                    *(uint32_t*)&Bh[r0 * BPITCH + px] =
                        hpack2(__float2half_rn(h00), __float2half_rn(h01));
                    *(uint32_t*)&Bh[(r0 + 8) * BPITCH + px] =
                        hpack2(__float2half_rn(h10), __float2half_rn(h11));
                    #pragma unroll
                    for (int r = 0; r < 4; r++) acc[s][jl][r] = 0.f;
                }
            }
            __syncthreads();   // H visible before GEMM2 reads B
        }

        // ---- compute chunk kc: 4 k-steps of 16; weights via LDG.128 fragments ----
        const uint4* wf = wfb + kc * 2048;
        const uint32_t bb = b_base + (uint32_t)((kc & 3) * 64) * (BPITCH * 2);
        #pragma unroll 2
        for (int ks = 0; ks < 4; ks++) {
            uint4 av = wf[ks * 32];
            const uint32_t bks = bb + (uint32_t)(ks * 16) * (BPITCH * 2);
            #pragma unroll
            for (int s = 0; s < 4; s++) {
                if (s >= ntiles) break;
                uint32_t bh[4];
                ldsm_x4_t(bh, bks + (uint32_t)(s * 16) * 2);   // col s*16 halfs
                mma_f16(acc[s][0], av.x, av.y, av.z, av.w, &bh[0]);
                mma_f16(acc[s][1], av.x, av.y, av.z, av.w, &bh[2]);
            }
        }
    }

    // ---- stage Y (bias added) into smem, aliasing Bh region ----
    __syncthreads();   // all warps done reading Bh
    float* Ys = (float*)(smc + SM_BH);   // [256][YPITCH] fp32 = 69632 B
    {
        int r0 = wid * 16 + g;
        float bv0 = b2g[r0], bv1 = b2g[r0 + 8];
        #pragma unroll
        for (int s = 0; s < 4; s++) {
            if (s >= ntiles) break;
            #pragma unroll
            for (int jl = 0; jl < 2; jl++) {
                int pc = s * 16 + jl * 8 + tc * 2;
                if (pc < nc) {
                    Ys[r0 * YPITCH + pc]       = acc[s][jl][0] + bv0;
                    Ys[(r0 + 8) * YPITCH + pc] = acc[s][jl][2] + bv1;
                }
                if (pc + 1 < nc) {
                    Ys[r0 * YPITCH + pc + 1]       = acc[s][jl][1] + bv0;
                    Ys[(r0 + 8) * YPITCH + pc + 1] = acc[s][jl][3] + bv1;
                }
            }
        }
    }
    __syncthreads();

    // ---- blended coalesced output: out = mask ? Y : x ----
    float* ob = out + (size_t)b * 256 * HW + p0;
    #pragma unroll 4
    for (int it = 0; it < 16; it++) {
        int e2 = tid + it * NTH;         // float2 index, 8192 total
        int c = e2 >> 5;                 // 32 float2 per 64-px row
        int q = (e2 & 31) * 2;
        float2 v = *(const float2*)(xb + (size_t)c * HW + q);
        float2 o = v;
        if (smc[SM_MSK + q])     o.x = Ys[c * YPITCH + pos[q]];
        if (smc[SM_MSK + q + 1]) o.y = Ys[c * YPITCH + pos[q + 1]];
        *(float2*)(ob + (size_t)c * HW + q) = o;
    }
}

extern "C" void kernel_launch(void* const* d_in, const int* in_sizes, int n_in,
                              void* d_out, int out_size)
{
    const float* x    = (const float*)d_in[0];
    const void*  mask = d_in[1];
    const float* W1   = (const float*)d_in[2];
    const float* b1   = (const float*)d_in[3];
    const float* W2   = (const float*)d_in[4];
    const float* b2   = (const float*)d_in[5];
    float*       out  = (float*)d_out;

    prep_weights_kernel<<<64, 256>>>(W1, W2);

    cudaFuncSetAttribute(mlp_mma_kernel,
                         cudaFuncAttributeMaxDynamicSharedMemorySize, SM_TOTAL);
    // 16 batches * 256 pixel tiles = 4096 CTAs, 2 CTAs/SM
    mlp_mma_kernel<<<4096, NTH, SM_TOTAL>>>(x, mask, b1, b2, out);
}

// round 16
// speedup vs baseline: 1.1868x; 1.1868x over previous
#include <cuda_runtime.h>
#include <cuda_fp16.h>
#include <cstdint>

#define HW 16384
#define NTH 512       // 16 warps per CTA; 2 CTAs/SM
#define PTILE 64      // pixels per CTA
#define BPITCH 72     // B smem pitch (halfs): 36 words = 4 mod 32 -> conflict-free ldsm
#define YPITCH 68     // Y smem pitch (floats)
#define NCHUNK 8      // 8 chunks of k=64: W1[0..3] then W2[4..7]

// ---- smem layout (bytes), per CTA ----
#define SM_BH   0                 // Bh fp16 256x72 = 36864; Ys fp32 256x68 = 69632 aliases [0,69632)
#define SM_MSK  69632             // 64
#define SM_POS  69760             // 64 x int16
#define SM_FLG  70016             // ints
#define SM_TOTAL 70080            // x2 CTAs = 140160

// Weights pre-packed in mma A-fragment order:
// g_Wf[(chunk*16 + wd)*4*32 + ks*32 + lane] = uint4{a0,a1,a2,a3} for that lane.
__device__ __align__(16) uint4 g_Wf[NCHUNK * 16 * 4 * 32];

__device__ __host__ __forceinline__ uint32_t hpack2(__half a, __half b) {
    __half2 t = __halves2half2(a, b);
    return *reinterpret_cast<uint32_t*>(&t);
}

// ---------------- weight prep: transpose + fp16 + fragment-order packing ----------------
extern "C" __global__ void prep_weights_kernel(const float* __restrict__ W1,
                                               const float* __restrict__ W2)
{
    int e = blockIdx.x * 256 + threadIdx.x;   // 0..16383
    int lane = e & 31;
    int ks   = (e >> 5) & 3;
    int wd   = (e >> 7) & 15;
    int ch   = e >> 11;                        // 0..7
    const float* W = (ch < 4) ? W1 : W2;       // A[m][k] = W[k*256 + m]
    int kb = (ch & 3) * 64 + ks * 16 + (lane & 3) * 2;
    int m0 = wd * 16 + (lane >> 2);

    uint4 v;
    v.x = hpack2(__float2half_rn(W[kb * 256 + m0]),
                 __float2half_rn(W[(kb + 1) * 256 + m0]));
    v.y = hpack2(__float2half_rn(W[kb * 256 + m0 + 8]),
                 __float2half_rn(W[(kb + 1) * 256 + m0 + 8]));
    v.z = hpack2(__float2half_rn(W[(kb + 8) * 256 + m0]),
                 __float2half_rn(W[(kb + 9) * 256 + m0]));
    v.w = hpack2(__float2half_rn(W[(kb + 8) * 256 + m0 + 8]),
                 __float2half_rn(W[(kb + 9) * 256 + m0 + 8]));
    g_Wf[e] = v;
}

// ---------------- helpers ----------------
__device__ __forceinline__ void ldsm_x4_t(uint32_t* r, uint32_t addr) {
    asm volatile("ldmatrix.sync.aligned.m8n8.x4.trans.shared.b16 {%0,%1,%2,%3}, [%4];"
                 : "=r"(r[0]), "=r"(r[1]), "=r"(r[2]), "=r"(r[3]) : "r"(addr));
}
__device__ __forceinline__ void mma_f16(float* d, uint32_t a0, uint32_t a1,
                                        uint32_t a2, uint32_t a3, const uint32_t* b) {
    asm volatile("mma.sync.aligned.m16n8k16.row.col.f32.f16.f16.f32 "
                 "{%0,%1,%2,%3}, {%4,%5,%6,%7}, {%8,%9}, {%0,%1,%2,%3};"
                 : "+f"(d[0]), "+f"(d[1]), "+f"(d[2]), "+f"(d[3])
                 : "r"(a0), "r"(a1), "r"(a2), "r"(a3), "r"(b[0]), "r"(b[1]));
}

// ---------------- templated branch-free MLP body ----------------
// NT = number of 16-pixel tiles (CTA-uniform). No data-dependent control flow inside.
template<int NT>
__device__ __forceinline__ void mlp_body(char* smc, const uint4* __restrict__ wfb,
                                         uint32_t b_base, int wid, int lane,
                                         const float* __restrict__ b1g,
                                         const float* __restrict__ b2g)
{
    const int g = lane >> 2, tc = lane & 3;
    __half* Bh = (__half*)(smc + SM_BH);

    float acc[NT][2][4];
    #pragma unroll
    for (int s = 0; s < NT; s++)
        #pragma unroll
        for (int jl = 0; jl < 2; jl++)
            #pragma unroll
            for (int r = 0; r < 4; r++) acc[s][jl][r] = 0.f;

    // ---- GEMM1: chunks 0..3 ----
    #pragma unroll 1
    for (int kci = 0; kci < 4; kci++) {
        const uint4* wf = wfb + kci * 2048;
        const uint32_t bb = b_base + (uint32_t)(kci * 64) * (BPITCH * 2);
        #pragma unroll 2
        for (int ks = 0; ks < 4; ks++) {
            uint4 av = wf[ks * 32];
            const uint32_t bks = bb + (uint32_t)(ks * 16) * (BPITCH * 2);
            #pragma unroll
            for (int s = 0; s < NT; s++) {
                uint32_t bh[4];
                ldsm_x4_t(bh, bks + (uint32_t)(s * 16) * 2);
                mma_f16(acc[s][0], av.x, av.y, av.z, av.w, &bh[0]);
                mma_f16(acc[s][1], av.x, av.y, av.z, av.w, &bh[2]);
            }
        }
    }

    // ---- H epilogue: bias + relu -> fp16 into Bh (unconditional; pad cols contained) ----
    __syncthreads();   // all warps done reading X from Bh
    {
        int r0 = wid * 16 + g;
        float bv0 = b1g[r0], bv1 = b1g[r0 + 8];
        #pragma unroll
        for (int s = 0; s < NT; s++)
            #pragma unroll
            for (int jl = 0; jl < 2; jl++) {
                int px = s * 16 + jl * 8 + tc * 2;
                float h00 = fmaxf(acc[s][jl][0] + bv0, 0.f);
                float h01 = fmaxf(acc[s][jl][1] + bv0, 0.f);
                float h10 = fmaxf(acc[s][jl][2] + bv1, 0.f);
                float h11 = fmaxf(acc[s][jl][3] + bv1, 0.f);
                *(uint32_t*)&Bh[r0 * BPITCH + px] =
                    hpack2(__float2half_rn(h00), __float2half_rn(h01));
                *(uint32_t*)&Bh[(r0 + 8) * BPITCH + px] =
                    hpack2(__float2half_rn(h10), __float2half_rn(h11));
                #pragma unroll
                for (int r = 0; r < 4; r++) acc[s][jl][r] = 0.f;
            }
    }
    __syncthreads();   // H visible before GEMM2 reads B

    // ---- GEMM2: chunks 4..7 ----
    #pragma unroll 1
    for (int kci = 0; kci < 4; kci++) {
        const uint4* wf = wfb + (4 + kci) * 2048;
        const uint32_t bb = b_base + (uint32_t)(kci * 64) * (BPITCH * 2);
        #pragma unroll 2
        for (int ks = 0; ks < 4; ks++) {
            uint4 av = wf[ks * 32];
            const uint32_t bks = bb + (uint32_t)(ks * 16) * (BPITCH * 2);
            #pragma unroll
            for (int s = 0; s < NT; s++) {
                uint32_t bh[4];
                ldsm_x4_t(bh, bks + (uint32_t)(s * 16) * 2);
                mma_f16(acc[s][0], av.x, av.y, av.z, av.w, &bh[0]);
                mma_f16(acc[s][1], av.x, av.y, av.z, av.w, &bh[2]);
            }
        }
    }

    // ---- stage Y (bias added) into smem, aliasing Bh (unconditional stores) ----
    __syncthreads();   // all warps done reading Bh
    float* Ys = (float*)(smc + SM_BH);   // [256][YPITCH] fp32
    {
        int r0 = wid * 16 + g;
        float bv0 = b2g[r0], bv1 = b2g[r0 + 8];
        #pragma unroll
        for (int s = 0; s < NT; s++)
            #pragma unroll
            for (int jl = 0; jl < 2; jl++) {
                int pc = s * 16 + jl * 8 + tc * 2;
                float2 y0 = make_float2(acc[s][jl][0] + bv0, acc[s][jl][1] + bv0);
                float2 y1 = make_float2(acc[s][jl][2] + bv1, acc[s][jl][3] + bv1);
                *(float2*)&Ys[r0 * YPITCH + pc]       = y0;
                *(float2*)&Ys[(r0 + 8) * YPITCH + pc] = y1;
            }
    }
}

// ---------------- main fused masked-MLP kernel ----------------
extern "C" __global__ void __launch_bounds__(NTH, 2)
mlp_mma_kernel(const float* __restrict__ x,
               const void* __restrict__ mask,
               const float* __restrict__ b1g,
               const float* __restrict__ b2g,
               float* __restrict__ out)
{
    extern __shared__ char smc[];
    const uint32_t sb = (uint32_t)__cvta_generic_to_shared(smc);
    int* flg = (int*)(smc + SM_FLG);
    short* pos = (short*)(smc + SM_POS);

    const int tid = threadIdx.x, lane = tid & 31, wid = tid >> 5;   // wid = wd 0..15
    const int l15 = lane & 15, l16 = (lane >> 4) * 8;
    const int b = blockIdx.x >> 8, p0 = (blockIdx.x & 255) * PTILE;
    const float* xb = x + (size_t)b * 256 * HW + p0;
    const int gi0 = b * HW + p0;

    // ---- per-CTA mask dtype detection (16 words cover 64 px in all encodings) ----
    if (tid < 16) {
        unsigned w = ((const unsigned*)mask)[gi0 / 4 + tid];
        bool fl = (w == 0x3F800000u);
        bool by = (w > 1u) && !fl;
        unsigned bb = __ballot_sync(0xFFFFu, by);
        if (tid == 0) flg[0] = bb ? 1 : 0;
    }
    __syncthreads();

    if (tid < PTILE) {
        int mv;
        if (flg[0]) mv = (((const unsigned char*)mask)[gi0 + tid] != 0);
        else        mv = (((const int*)mask)[gi0 + tid] != 0);
        smc[SM_MSK + tid] = (char)mv;
    }
    __syncthreads();

    // ---- warp 0: prefix scan over 64 px -> per-pixel pos[] / nc ----
    if (wid == 0) {
        int base = lane * 2;
        int m0 = smc[SM_MSK + base], m1 = smc[SM_MSK + base + 1];
        int c = m0 + m1;
        int sc = c;
        #pragma unroll
        for (int o = 1; o < 32; o <<= 1) {
            int t = __shfl_up_sync(0xFFFFFFFFu, sc, o);
            if (lane >= o) sc += t;
        }
        int run = sc - c;
        pos[base]     = (short)run; run += m0;
        pos[base + 1] = (short)run; run += m1;
        if (lane == 31) flg[1] = run;
    }
    __syncthreads();
    const int nc = flg[1];
    const int ntiles = (nc + 15) >> 4;   // 0..4, CTA-uniform

    // ---- X load + fp16 convert + compacted store ----
    __half* Bh = (__half*)(smc + SM_BH);
    #pragma unroll 4
    for (int it = 0; it < 8; it++) {
        int e = tid + it * NTH;          // 0..4095 float4s
        int c = e >> 4;                  // 16 float4 per 64-px row
        int q = (e & 15) * 4;
        float4 v = *(const float4*)(xb + (size_t)c * HW + q);
        float vv[4] = {v.x, v.y, v.z, v.w};
        #pragma unroll
        for (int i = 0; i < 4; i++) {
            if (smc[SM_MSK + q + i])
                Bh[c * BPITCH + pos[q + i]] = __float2half_rn(vv[i]);
        }
    }
    __syncthreads();   // X tile visible to all warps before B-ldsm

    const uint4* __restrict__ wfb = g_Wf + (wid << 7) + lane;
    const uint32_t b_base = sb + SM_BH + (uint32_t)(l15 * BPITCH + l16) * 2;

    // ---- CTA-uniform dispatch on tile count: branch-free inner bodies ----
    switch (ntiles) {
        case 4: mlp_body<4>(smc, wfb, b_base, wid, lane, b1g, b2g); break;
        case 3: mlp_body<3>(smc, wfb, b_base, wid, lane, b1g, b2g); break;
        case 2: mlp_body<2>(smc, wfb, b_base, wid, lane, b1g, b2g); break;
        case 1: mlp_body<1>(smc, wfb, b_base, wid, lane, b1g, b2g); break;
        default: break;   // ntiles == 0: nothing masked
    }
    __syncthreads();

    // ---- blended coalesced output: out = mask ? Y : x (predicated selects) ----
    float* Ys = (float*)(smc + SM_BH);
    float* ob = out + (size_t)b * 256 * HW + p0;
    #pragma unroll 4
    for (int it = 0; it < 16; it++) {
        int e2 = tid + it * NTH;         // float2 index, 8192 total
        int c = e2 >> 5;                 // 32 float2 per 64-px row
        int q = (e2 & 31) * 2;
        float2 v = *(const float2*)(xb + (size_t)c * HW + q);
        float y0 = Ys[c * YPITCH + pos[q]];
        float y1 = Ys[c * YPITCH + pos[q + 1]];
        float2 o;
        o.x = smc[SM_MSK + q]     ? y0 : v.x;
        o.y = smc[SM_MSK + q + 1] ? y1 : v.y;
        *(float2*)(ob + (size_t)c * HW + q) = o;
    }
}

extern "C" void kernel_launch(void* const* d_in, const int* in_sizes, int n_in,
                              void* d_out, int out_size)
{
    const float* x    = (const float*)d_in[0];
    const void*  mask = d_in[1];
    const float* W1   = (const float*)d_in[2];
    const float* b1   = (const float*)d_in[3];
    const float* W2   = (const float*)d_in[4];
    const float* b2   = (const float*)d_in[5];
    float*       out  = (float*)d_out;

    prep_weights_kernel<<<64, 256>>>(W1, W2);

    cudaFuncSetAttribute(mlp_mma_kernel,
                         cudaFuncAttributeMaxDynamicSharedMemorySize, SM_TOTAL);
    // 16 batches * 256 pixel tiles = 4096 CTAs, 2 CTAs/SM
    mlp_mma_kernel<<<4096, NTH, SM_TOTAL>>>(x, mask, b1, b2, out);
}